// round 12
// baseline (speedup 1.0000x reference)
#include <cuda_runtime.h>

// ============================================================================
// STGCNEncoder — fused persistent kernel, v5.
// Only row 0 of the GCN output feeds the GRU.
// Both dst streams now go through cp.async.bulk (TMA path, bypasses the
// per-SM L1-miss-queue ceiling that capped LDG streaming at ~2.5 TB/s):
//  Pass A: bulk 16KB chunks -> smem, scan for dst==0, collect srcs.
//  Pass B: u8 presence table (100KB smem) + bulk chunks -> exact degrees.
//  Pass-B chunks are prefetched across barrier 1. Encoder GEMVs + gh overlap,
//  block-0 tail. 3 grid barriers. B=1024, 1 block/SM.
// ============================================================================

#define G     148
#define B     1024
#define SLOTS 6
#define CHUNK 16384
#define CAP   2048

__device__ unsigned long long g_bar;
__device__ int   g_cnt;
__device__ int   g_srcs[CAP];
__device__ int   g_nodecnt[CAP + 2];
__device__ unsigned short g_pres[131072];   // fallback presence (rare path)
__device__ float g_ybuf[CAP + 1][128];
__device__ float g_gh[768];

extern __shared__ char sMem[];   // [0,NPAD): u8 table | [NPAD, NPAD+SLOTS*CHUNK): ring

__device__ __forceinline__ unsigned sm2u(const void* p) {
    unsigned r;
    asm("{.reg .u64 t; cvta.to.shared.u64 t, %1; cvt.u32.u64 %0, t;}" : "=r"(r) : "l"(p));
    return r;
}
__device__ __forceinline__ void mb_init(unsigned a) {
    asm volatile("mbarrier.init.shared.b64 [%0], 1;" :: "r"(a) : "memory");
}
__device__ __forceinline__ void mb_expect(unsigned a, unsigned bytes) {
    asm volatile("mbarrier.arrive.expect_tx.shared.b64 _, [%0], %1;" :: "r"(a), "r"(bytes) : "memory");
}
__device__ __forceinline__ void bulk_g2s(unsigned dst, const void* src, unsigned bytes, unsigned mbar) {
    asm volatile("cp.async.bulk.shared::cluster.global.mbarrier::complete_tx::bytes [%0], [%1], %2, [%3];"
                 :: "r"(dst), "l"(src), "r"(bytes), "r"(mbar) : "memory");
}
__device__ __forceinline__ void mb_wait(unsigned a, unsigned parity) {
    unsigned done;
    asm volatile("{.reg .pred p; mbarrier.try_wait.parity.acquire.cta.shared::cta.b64 p, [%1], %2; selp.b32 %0,1,0,p;}"
                 : "=r"(done) : "r"(a), "r"(parity) : "memory");
    while (!done)
        asm volatile("{.reg .pred p; mbarrier.try_wait.parity.acquire.cta.shared::cta.b64 p, [%1], %2, 0x989680; selp.b32 %0,1,0,p;}"
                     : "=r"(done) : "r"(a), "r"(parity) : "memory");
}

__device__ __forceinline__ void gbar() {
    __threadfence();
    __syncthreads();
    if (threadIdx.x == 0) {
        unsigned long long t = atomicAdd(&g_bar, 1ULL);
        unsigned long long target = t - (t % G) + G;
        volatile unsigned long long* p = &g_bar;
        while (*p < target) {}
    }
    __syncthreads();
    __threadfence();
}

__global__ void __launch_bounds__(B, 1) k_fused(
    const float* __restrict__ nf, const float* __restrict__ h,
    const float* __restrict__ W_enc, const float* __restrict__ b_enc,
    const float* __restrict__ W_gcn, const float* __restrict__ b_gcn,
    const float* __restrict__ W_ih, const float* __restrict__ W_hh,
    const float* __restrict__ b_ih, const float* __restrict__ b_hh,
    const unsigned* __restrict__ w, int E, int N, float* __restrict__ out)
{
    __shared__ unsigned long long smb[SLOTS];
    __shared__ int   sS[CAP];
    __shared__ int   sBad;
    __shared__ float sF[64];

    const int t = threadIdx.x, lane = t & 31, wid = t >> 5;
    const int bid = blockIdx.x;
    const int NPAD = (N + 15) & ~15;
    unsigned char* sT8 = (unsigned char*)sMem;

    // ---- init: zero u8 table, init mbarriers, dtype detect ----
    {
        uint4* p4 = (uint4*)sMem;
        uint4 z = make_uint4(0, 0, 0, 0);
        for (int i = t; i < NPAD >> 4; i += B) p4[i] = z;
    }
    if (t == 0) {
        sBad = 0;
        for (int s = 0; s < SLOTS; s++) mb_init(sm2u(&smb[s]));
    }
    __syncthreads();
    {
        int bad = 0;
        for (int i = t; i < 2048 && i < E; i += B) bad |= (int)w[2 * i + 1];
        if (bad) atomicOr(&sBad, 1);
    }
    __syncthreads();
    const bool is64 = (sBad == 0);
    const bool fastA = is64 ? ((E & 1) == 0) : ((E & 3) == 0);

    const size_t dbytes = (size_t)(is64 ? 8 : 4) * (size_t)E;
    const char* dstBase = (const char*)w + dbytes;      // dst follows src
    const long long* srcq = (const long long*)w;
    const int* srci = (const int*)w;

    unsigned mbA[SLOTS];
    #pragma unroll
    for (int s = 0; s < SLOTS; s++) mbA[s] = sm2u(&smb[s]);
    const unsigned bufA = sm2u(sMem) + NPAD;

    int NC = (int)((dbytes + CHUNK - 1) / CHUNK);
    int RA = (bid < NC) ? ((NC - 1 - bid) / G + 1) : 0;
    const int RT = 2 * RA;

    // issue helper (macro to keep it inlined per call site)
#define ISSUE(rr) { \
    int c_ = ((rr) < RA) ? (bid + (rr) * G) : (bid + ((rr) - RA) * G); \
    unsigned co_ = (unsigned)c_ * CHUNK; \
    unsigned cs_ = (unsigned)((dbytes - co_ < CHUNK) ? (dbytes - co_) : CHUNK); \
    int s_ = (rr) % SLOTS; \
    mb_expect(mbA[s_], cs_); \
    bulk_g2s(bufA + s_ * CHUNK, dstBase + co_, cs_, mbA[s_]); }

    // ---------------- Pass A ----------------
    if (fastA) {
        if (t == 0) {
            int pr = RT < SLOTS ? RT : SLOTS;
            for (int rr = 0; rr < pr; rr++) ISSUE(rr);
        }
        for (int rr = 0; rr < RA; rr++) {
            int cidx = bid + rr * G;
            unsigned coff = (unsigned)cidx * CHUNK;
            unsigned csz = (unsigned)((dbytes - coff < CHUNK) ? (dbytes - coff) : CHUNK);
            int s = rr % SLOTS;
            mb_wait(mbA[s], (rr / SLOTS) & 1);
            const uint4* bp = (const uint4*)(sMem + NPAD + s * CHUNK);
            int n = csz >> 4;
            if (is64) {
                long ebase = (long)(coff >> 3);
                for (int i = t; i < n; i += B) {
                    uint4 v = bp[i];
                    if (min(v.x, v.z) == 0) {
                        long e = ebase + 2L * i;
                        if (v.x == 0) { int p = atomicAdd(&g_cnt, 1); if (p < CAP) g_srcs[p] = (int)srcq[e]; }
                        if (v.z == 0) { int p = atomicAdd(&g_cnt, 1); if (p < CAP) g_srcs[p] = (int)srcq[e + 1]; }
                    }
                }
            } else {
                long ebase = (long)(coff >> 2);
                for (int i = t; i < n; i += B) {
                    uint4 v = bp[i];
                    if (min(min(v.x, v.y), min(v.z, v.w)) == 0) {
                        long e = ebase + 4L * i;
                        if (v.x == 0) { int p = atomicAdd(&g_cnt, 1); if (p < CAP) g_srcs[p] = srci[e]; }
                        if (v.y == 0) { int p = atomicAdd(&g_cnt, 1); if (p < CAP) g_srcs[p] = srci[e + 1]; }
                        if (v.z == 0) { int p = atomicAdd(&g_cnt, 1); if (p < CAP) g_srcs[p] = srci[e + 2]; }
                        if (v.w == 0) { int p = atomicAdd(&g_cnt, 1); if (p < CAP) g_srcs[p] = srci[e + 3]; }
                    }
                }
            }
            __syncthreads();
            if (t == 0 && rr + SLOTS < RT) ISSUE(rr + SLOTS);   // may prefetch pass B
        }
    } else {
        // scalar fallback pass A
        if (is64) {
            const long long* dst = srcq + E;
            for (long i = (long)bid * B + t; i < E; i += (long)G * B)
                if (dst[i] == 0) { int p = atomicAdd(&g_cnt, 1); if (p < CAP) g_srcs[p] = (int)srcq[i]; }
        } else {
            const int* dst = srci + E;
            for (long i = (long)bid * B + t; i < E; i += (long)G * B)
                if (dst[i] == 0) { int p = atomicAdd(&g_cnt, 1); if (p < CAP) g_srcs[p] = srci[i]; }
        }
    }
    gbar();  // -------- barrier 1 --------

    int cnt = g_cnt; if (cnt > CAP) cnt = CAP;
    const int M = cnt + 1;
    const bool fastB = fastA && (cnt <= 253);

    // stage srcs into smem (needed by encoder + table build)
    for (int i = t; i < cnt; i += B) sS[i] = g_srcs[i];
    __syncthreads();

    // ---------------- Pass B ----------------
    if (fastB) {
        // parallel u8 table build (duplicate races are value-equivalent)
        for (int i = t; i < cnt; i += B) sT8[sS[i]] = (unsigned char)(i + 1);
        __syncthreads();
        if (t == 0 && sT8[0] == 0) sT8[0] = (unsigned char)(cnt + 1);
        __syncthreads();

        for (int rr = RA; rr < RT; rr++) {
            int cidx = bid + (rr - RA) * G;
            unsigned coff = (unsigned)cidx * CHUNK;
            unsigned csz = (unsigned)((dbytes - coff < CHUNK) ? (dbytes - coff) : CHUNK);
            int s = rr % SLOTS;
            mb_wait(mbA[s], (rr / SLOTS) & 1);
            const uint4* bp = (const uint4*)(sMem + NPAD + s * CHUNK);
            int n = csz >> 4;
            if (is64) {
                for (int i = t; i < n; i += B) {
                    uint4 v = bp[i];
                    unsigned p0 = sT8[v.x], p1 = sT8[v.z];
                    if (p0 | p1) {
                        if (p0) atomicAdd(&g_nodecnt[p0 - 1], 1);
                        if (p1) atomicAdd(&g_nodecnt[p1 - 1], 1);
                    }
                }
            } else {
                for (int i = t; i < n; i += B) {
                    uint4 v = bp[i];
                    unsigned p0 = sT8[v.x], p1 = sT8[v.y], p2 = sT8[v.z], p3 = sT8[v.w];
                    if ((p0 | p1) | (p2 | p3)) {
                        if (p0) atomicAdd(&g_nodecnt[p0 - 1], 1);
                        if (p1) atomicAdd(&g_nodecnt[p1 - 1], 1);
                        if (p2) atomicAdd(&g_nodecnt[p2 - 1], 1);
                        if (p3) atomicAdd(&g_nodecnt[p3 - 1], 1);
                    }
                }
            }
            __syncthreads();
            if (t == 0 && rr + SLOTS < RT) ISSUE(rr + SLOTS);
        }
    } else {
        // fallback: global u16 presence table + scalar LDG scan
        for (int i = bid * B + t; i < NPAD && i < 131072; i += G * B) g_pres[i] = 0;
        gbar();
        if (bid == 0 && t == 0) {
            for (int i = 0; i < cnt; i++) g_pres[sS[i]] = (unsigned short)(i + 1);
            if (g_pres[0] == 0) g_pres[0] = (unsigned short)(cnt + 1);
        }
        gbar();
        if (is64) {
            const long long* dst = srcq + E;
            for (long i = (long)bid * B + t; i < E; i += (long)G * B) {
                unsigned p = g_pres[(unsigned)dst[i]];
                if (p) atomicAdd(&g_nodecnt[p - 1], 1);
            }
        } else {
            const int* dst = srci + E;
            for (long i = (long)bid * B + t; i < E; i += (long)G * B) {
                unsigned p = g_pres[(unsigned)dst[i]];
                if (p) atomicAdd(&g_nodecnt[p - 1], 1);
            }
        }
    }
    gbar();  // -------- barrier 2 --------

    // ---------------- Encoder terms (block per term) + gh overlap ----------
    if (bid < M) {
        unsigned pi0 = fastB ? (unsigned)sT8[0] : (unsigned)g_pres[0];
        const float rd0 = rsqrtf((float)g_nodecnt[pi0 - 1] + 1.0f);
        for (int i = bid; i < M; i += G) {
            int s = (i < cnt) ? sS[i] : 0;
            unsigned pis = fastB ? (unsigned)sT8[s] : (unsigned)g_pres[s];
            float wt = rsqrtf((float)g_nodecnt[pis - 1] + 1.0f) * rd0;
            if (t < 64) sF[t] = nf[(long)s * 64 + t];
            __syncthreads();
            float f0 = sF[lane], f1 = sF[lane + 32];
            #pragma unroll
            for (int jj = 0; jj < 4; jj++) {
                int j = wid * 4 + jj;
                const float* wr = W_enc + j * 64;
                float a = wr[lane] * f0 + wr[lane + 32] * f1;
                #pragma unroll
                for (int o = 16; o; o >>= 1) a += __shfl_down_sync(0xffffffffu, a, o);
                if (lane == 0) g_ybuf[i][j] = wt * fmaxf(a + b_enc[j], 0.0f);
            }
            __syncthreads();
        }
    }
    if (bid >= 96) {                      // gh = W_hh @ h + b_hh (indep of g0)
        int r = (bid - 96) * 32 + wid;
        if (r < 768) {
            const float* wr = W_hh + r * 256;
            float a = 0.0f;
            #pragma unroll
            for (int kk = 0; kk < 8; kk++) a += wr[kk * 32 + lane] * h[kk * 32 + lane];
            #pragma unroll
            for (int o = 16; o; o >>= 1) a += __shfl_down_sync(0xffffffffu, a, o);
            if (lane == 0) g_gh[r] = a + b_hh[r];
        }
    }
    gbar();  // -------- barrier 3 --------

    // ---------------- Block-0 tail: xsum, g0, gi, gates, reset -------------
    if (bid == 0) {
        float* sX   = (float*)sMem;       // table no longer needed
        float* sG0  = sX + 128;
        float* sGi  = sG0 + 128;          // 768 floats
        float* sPar = sX + 1024;          // 8 x 128 partials

        {
            int grp = t >> 7, col = t & 127;
            float xs = 0.0f;
            for (int i = grp; i < M; i += 8) xs += g_ybuf[i][col];
            sPar[grp * 128 + col] = xs;
        }
        __syncthreads();
        if (t < 128) {
            float s = 0.0f;
            #pragma unroll
            for (int g2 = 0; g2 < 8; g2++) s += sPar[g2 * 128 + t];
            sX[t] = s;
        }
        __syncthreads();
        #pragma unroll
        for (int jj = 0; jj < 4; jj++) {
            int j = wid * 4 + jj;
            float a = 0.0f;
            #pragma unroll
            for (int kk = 0; kk < 4; kk++)
                a += W_gcn[j * 128 + kk * 32 + lane] * sX[kk * 32 + lane];
            #pragma unroll
            for (int o = 16; o; o >>= 1) a += __shfl_down_sync(0xffffffffu, a, o);
            if (lane == 0) sG0[j] = fmaxf(a + b_gcn[j], 0.0f);
        }
        __syncthreads();
        #pragma unroll
        for (int q = 0; q < 24; q++) {
            int r = q * 32 + wid;
            const float* wr = W_ih + r * 128;
            float a = 0.0f;
            #pragma unroll
            for (int kk = 0; kk < 4; kk++)
                a += wr[kk * 32 + lane] * sG0[kk * 32 + lane];
            #pragma unroll
            for (int o = 16; o; o >>= 1) a += __shfl_down_sync(0xffffffffu, a, o);
            if (lane == 0) sGi[r] = a + b_ih[r];
        }
        __syncthreads();
        if (t < 256) {
            float r_ = 1.0f / (1.0f + expf(-(sGi[t] + g_gh[t])));
            float z  = 1.0f / (1.0f + expf(-(sGi[256 + t] + g_gh[256 + t])));
            float nn = tanhf(sGi[512 + t] + r_ * g_gh[512 + t]);
            out[t] = (1.0f - z) * nn + z * h[t];
        }
        for (int i = t; i < cnt + 2; i += B) g_nodecnt[i] = 0;
        if (t == 0) g_cnt = 0;
    }
}

// ---------------------------------------------------------------------------
extern "C" void kernel_launch(void* const* d_in, const int* in_sizes, int n_in,
                              void* d_out, int out_size) {
    const float* nf    = (const float*)d_in[0];
    // d_in[1] = edge_attr (unused by reference)
    const float* h     = (const float*)d_in[2];
    const float* W_enc = (const float*)d_in[3];
    const float* b_enc = (const float*)d_in[4];
    const float* W_gcn = (const float*)d_in[5];
    const float* b_gcn = (const float*)d_in[6];
    const float* W_ih  = (const float*)d_in[7];
    const float* W_hh  = (const float*)d_in[8];
    const float* b_ih  = (const float*)d_in[9];
    const float* b_hh  = (const float*)d_in[10];
    const unsigned* ei = (const unsigned*)d_in[11];
    int E = in_sizes[11] / 2;
    int N = in_sizes[0] / 64;
    float* out = (float*)d_out;

    int npad = (N + 15) & ~15;
    int smem = npad + SLOTS * CHUNK;
    if (smem < 16384) smem = 16384;
    cudaFuncSetAttribute(k_fused, cudaFuncAttributeMaxDynamicSharedMemorySize, smem);

    k_fused<<<G, B, smem>>>(nf, h, W_enc, b_enc, W_gcn, b_gcn,
                            W_ih, W_hh, b_ih, b_hh, ei, E, N, out);
}